// round 15
// baseline (speedup 1.0000x reference)
#include <cuda_runtime.h>

#define T_STEPS 784
#define HDIM    110
#define G4      440
#define NTH     480
#define NCLS    10

// ---------- f32x2 packed helpers ----------
__device__ __forceinline__ unsigned long long pk2(float x, float y) {
    unsigned long long r;
    asm("mov.b64 %0, {%1,%2};" : "=l"(r) : "f"(x), "f"(y));
    return r;
}
__device__ __forceinline__ float2 upk2(unsigned long long a) {
    float2 r;
    asm("mov.b64 {%0,%1}, %2;" : "=f"(r.x), "=f"(r.y) : "l"(a));
    return r;
}
__device__ __forceinline__ void ff2(unsigned long long& acc,
                                    unsigned long long a,
                                    unsigned long long b) {
    asm("fma.rn.f32x2 %0, %1, %2, %0;" : "+l"(acc) : "l"(a), "l"(b));
}

// ---------- activations ----------
__device__ __forceinline__ float tanha(float x) {          // MUFU.TANH
    float r;
    asm("tanh.approx.f32 %0, %1;" : "=f"(r) : "f"(x));
    return r;
}
__device__ __forceinline__ float sigmf(float x) {          // fast gate sigmoid
    return fmaf(0.5f, tanha(0.5f * x), 0.5f);
}
__device__ __forceinline__ float sigm_precise(float x) {   // du decision path
    return __fdividef(1.0f, 1.0f + __expf(-x));
}

__global__ void zero_slot_kernel(float* o, int idx) { o[idx] = 0.0f; }

__global__ void __launch_bounds__(NTH, 1) skiplstm_kernel(
    const float* __restrict__ x,      // [B, T, 1]
    const float* __restrict__ Wih,    // [440, 1]
    const float* __restrict__ Whh,    // [440, 110]
    const float* __restrict__ bg,     // [440]
    const float* __restrict__ Wp,     // [1, 110]
    const float* __restrict__ bp_,    // [1]
    const float* __restrict__ h0,     // [110]
    const float* __restrict__ c0,     // [110]
    const float* __restrict__ Wfc,    // [10, 110]
    const float* __restrict__ bfc,    // [10]
    float* __restrict__ out,          // [B*10 + 1]
    int last_idx)
{
    __shared__ float sx[2][T_STEPS];                    // x sequences
    __shared__ __align__(16) float smh[2][2][112];      // h [lane][parity][dim]
    __shared__ __align__(16) float smc[2][112];         // c [lane][dim]
    __shared__ float swp[112];                          // W_p (zero-padded)
    __shared__ float swih[G4];                          // W_ih column
    __shared__ float sbj[G4];                           // gate bias
    __shared__ float sflags[2];                         // activity flags

    const int tid  = threadIdx.x;
    const int warp = tid >> 5, lane = tid & 31;
    const int b0g  = blockIdx.x * 2;

    for (int i = tid; i < T_STEPS; i += NTH) {
        sx[0][i] = x[b0g * T_STEPS + i];
        sx[1][i] = x[(b0g + 1) * T_STEPS + i];
    }
    for (int i = tid; i < 112; i += NTH) {
        float hv = (i < HDIM) ? h0[i] : 0.0f;
        float cv = (i < HDIM) ? c0[i] : 0.0f;
        smh[0][0][i] = hv; smh[0][1][i] = 0.0f;         // pads stay 0
        smh[1][0][i] = hv; smh[1][1][i] = 0.0f;
        smc[0][i] = cv;    smc[1][i] = cv;
        swp[i] = (i < HDIM) ? Wp[i] : 0.0f;
    }
    if (tid < G4) {
        swih[tid] = Wih[tid];
        sbj[tid]  = bg[tid];
    }
    if (tid == 0) { sflags[0] = 1.0f; sflags[1] = 1.0f; }
    const float bp = bp_[0];
    __syncthreads();

    int totu = 0;

    if (warp < 14) {
        // ============ GEMV + fused pointwise (warps 0-13) ============
        const int d    = warp * 8 + (lane >> 2);        // my hidden dim
        const int g    = lane & 3;                      // my gate
        const bool dv  = (d < HDIM);
        const int row  = g * HDIM + (dv ? d : 0);

        unsigned long long w[55];                       // only on this path
        {
            const float* wr = Whh + row * HDIM;
#pragma unroll
            for (int k = 0; k < 55; k++)
                w[k] = dv ? pk2(wr[2 * k], wr[2 * k + 1]) : 0ull;
        }
        const float wi = swih[row];
        const float bj = sbj[row];

        for (int t = 0; t < T_STEPS; t++) {
            const int rp = t & 1, wp2 = rp ^ 1;
#pragma unroll
            for (int l = 0; l < 2; l++) {               // phase A: l=0, B: l=1
                const float* hsrc = smh[l][rp];
                const ulonglong2* hq = (const ulonglong2*)hsrc;
                unsigned long long ax = 0ull, ay = 0ull;
#pragma unroll
                for (int k = 0; k < 27; k++) {
                    ulonglong2 hv = hq[k];
                    ff2(ax, w[2 * k],     hv.x);
                    ff2(ay, w[2 * k + 1], hv.y);
                }
                ff2(ax, w[54], ((const unsigned long long*)hsrc)[54]);
                float2 vx = upk2(ax), vy = upk2(ay);
                float val = (vx.x + vx.y) + (vy.x + vy.y)
                          + fmaf(sx[l][t], wi, bj);

                // activation of MY gate, then quad exchange (3 shfl)
                float actv = (g == 2) ? tanha(val) : sigmf(val);
                float v1 = __shfl_xor_sync(0xffffffffu, actv, 1);
                float q0 = __shfl_xor_sync(0xffffffffu, actv, 2);
                float q1 = __shfl_xor_sync(0xffffffffu, v1,   2);
                // at g==0: actv=i_, v1=f_, q0=g_, q1=o_

                if (g == 0 && dv) {
                    const bool act = (sflags[l] != 0.0f);
                    float c_old = smc[l][d];
                    float h_old = hsrc[d];
                    float cn = fmaf(v1, c_old, actv * q0);
                    float cw = act ? cn : c_old;
                    float hw = act ? (q1 * tanha(cn)) : h_old;
                    smc[l][d]       = cw;
                    smh[l][wp2][d]  = hw;
                }
                __syncthreads();
            }
        }
    } else {
        // ============ du / u / flags (warp 14) ============
        float u0 = 1.0f, u1 = 1.0f;
        bool  a0 = true, a1 = true;
        totu = 2;                                       // t=0, both lanes

        for (int t = 0; t < T_STEPS; t++) {
            // phase A: compute flag1 for step t (from smc1 = state t-1)
            if (t > 0) {
                float p = 0.0f;
                for (int dd = lane; dd < HDIM; dd += 32)
                    p = fmaf(smc[1][dd], swp[dd], p);
#pragma unroll
                for (int off = 16; off; off >>= 1)
                    p += __shfl_xor_sync(0xffffffffu, p, off);
                float du = sigm_precise(p + bp);
                u1 = a1 ? du : u1 + fminf(du, 1.0f - u1);
                a1 = (rintf(u1) != 0.0f);
                totu += a1 ? 1 : 0;
                if (lane == 0) sflags[1] = a1 ? 1.0f : 0.0f;
            }
            __syncthreads();
            // phase B: compute flag0 for step t+1 (from smc0 = state t)
            if (t < T_STEPS - 1) {
                float p = 0.0f;
                for (int dd = lane; dd < HDIM; dd += 32)
                    p = fmaf(smc[0][dd], swp[dd], p);
#pragma unroll
                for (int off = 16; off; off >>= 1)
                    p += __shfl_xor_sync(0xffffffffu, p, off);
                float du = sigm_precise(p + bp);
                u0 = a0 ? du : u0 + fminf(du, 1.0f - u0);
                a0 = (rintf(u0) != 0.0f);
                totu += a0 ? 1 : 0;
                if (lane == 0) sflags[0] = a0 ? 1.0f : 0.0f;
            }
            __syncthreads();
        }
    }
    __syncthreads();

    // ---- FC head: final h parity = (784)&1 = 0 ----
    for (int pi = warp; pi < 2 * NCLS; pi += NTH / 32) {
        const int b = pi / NCLS, cls = pi % NCLS;
        const float* wf = Wfc + cls * HDIM;
        float s = 0.0f;
        for (int dd = lane; dd < HDIM; dd += 32) s += smh[b][0][dd] * wf[dd];
#pragma unroll
        for (int off = 16; off; off >>= 1)
            s += __shfl_xor_sync(0xffffffffu, s, off);
        if (lane == 0) out[(b0g + b) * NCLS + cls] = s + bfc[cls];
    }

    // total_u from warp 14 (all lanes identical; add once)
    if (warp == 14 && lane == 0) atomicAdd(&out[last_idx], (float)totu);
}

extern "C" void kernel_launch(void* const* d_in, const int* in_sizes, int n_in,
                              void* d_out, int out_size) {
    const float* x    = (const float*)d_in[0];
    const float* Wih  = (const float*)d_in[1];
    const float* Whh  = (const float*)d_in[2];
    const float* bg   = (const float*)d_in[3];
    const float* Wp   = (const float*)d_in[4];
    const float* bp   = (const float*)d_in[5];
    const float* h0   = (const float*)d_in[6];
    const float* c0   = (const float*)d_in[7];
    const float* Wfc  = (const float*)d_in[8];
    const float* bfc  = (const float*)d_in[9];
    float* out = (float*)d_out;

    const int B = in_sizes[0] / T_STEPS;   // I = 1
    const int last = out_size - 1;

    zero_slot_kernel<<<1, 1>>>(out, last);
    skiplstm_kernel<<<B / 2, NTH>>>(x, Wih, Whh, bg, Wp, bp, h0, c0,
                                    Wfc, bfc, out, last);
}

// round 16
// speedup vs baseline: 1.2366x; 1.2366x over previous
#include <cuda_runtime.h>

#define T_STEPS 784
#define HDIM    110
#define G4      440
#define NTH     512
#define NCLS    10

// ---------- f32x2 packed helpers ----------
__device__ __forceinline__ unsigned long long pk2(float x, float y) {
    unsigned long long r;
    asm("mov.b64 %0, {%1,%2};" : "=l"(r) : "f"(x), "f"(y));
    return r;
}
__device__ __forceinline__ float2 upk2(unsigned long long a) {
    float2 r;
    asm("mov.b64 {%0,%1}, %2;" : "=f"(r.x), "=f"(r.y) : "l"(a));
    return r;
}
__device__ __forceinline__ void ff2(unsigned long long& acc,
                                    unsigned long long a,
                                    unsigned long long b) {
    asm("fma.rn.f32x2 %0, %1, %2, %0;" : "+l"(acc) : "l"(a), "l"(b));
}

// ---------- activations ----------
__device__ __forceinline__ float tanha(float x) {          // MUFU.TANH
    float r;
    asm("tanh.approx.f32 %0, %1;" : "=f"(r) : "f"(x));
    return r;
}
__device__ __forceinline__ float sigmf(float x) {          // fast gate sigmoid
    return fmaf(0.5f, tanha(0.5f * x), 0.5f);
}
__device__ __forceinline__ float sigm_precise(float x) {   // du decision path
    return __fdividef(1.0f, 1.0f + __expf(-x));
}

__global__ void zero_slot_kernel(float* o, int idx) { o[idx] = 0.0f; }

__global__ void __launch_bounds__(NTH, 1) skiplstm_kernel(
    const float* __restrict__ x,      // [B, T, 1]
    const float* __restrict__ Wih,    // [440, 1]
    const float* __restrict__ Whh,    // [440, 110]
    const float* __restrict__ bg,     // [440]
    const float* __restrict__ Wp,     // [1, 110]
    const float* __restrict__ bp_,    // [1]
    const float* __restrict__ h0,     // [110]
    const float* __restrict__ c0,     // [110]
    const float* __restrict__ Wfc,    // [10, 110]
    const float* __restrict__ bfc,    // [10]
    float* __restrict__ out,          // [B*10 + 1]
    int last_idx)
{
    __shared__ float sx[2][T_STEPS];                 // per-batch x sequence
    __shared__ __align__(16) float smh[2][112];      // h state (pads=0)
    __shared__ __align__(16) float smc[2][112];      // c state (pads=0)
    __shared__ float smgA[G4];                       // gates, batch lane 0
    __shared__ float smgB[G4];                       // gates, batch lane 1
    __shared__ float swp[112];                       // W_p (zero-padded)
    __shared__ float swih[G4];                       // W_ih column
    __shared__ float sbj[G4];                        // gate bias
    __shared__ float spart[2][2];                    // du partials [lane][pw-warp]

    const int tid  = threadIdx.x;
    const int warp = tid >> 5, lane = tid & 31;
    const int b0g  = blockIdx.x * 2;

    for (int i = tid; i < T_STEPS; i += NTH) {
        sx[0][i] = x[b0g * T_STEPS + i];
        sx[1][i] = x[(b0g + 1) * T_STEPS + i];
    }
    for (int i = tid; i < 112; i += NTH) {
        float hv = (i < HDIM) ? h0[i] : 0.0f;
        float cv = (i < HDIM) ? c0[i] : 0.0f;
        smh[0][i] = hv; smh[1][i] = hv;
        smc[0][i] = cv; smc[1][i] = cv;
        swp[i] = (i < HDIM) ? Wp[i] : 0.0f;
    }
    if (tid < G4) {
        swih[tid] = Wih[tid];
        sbj[tid]  = bg[tid];
    }
    const float bp = bp_[0];
    __syncthreads();

    int totu = 0;

    if (warp < 14) {
        // ================= GEMV role (warps 0-13) — identical to R13 =====
        const bool gvv = (tid < G4);
        unsigned long long w[55];                    // loaded ONLY on this path
        {
            const float* wr = Whh + (gvv ? tid : 0) * HDIM;
#pragma unroll
            for (int k = 0; k < 55; k++)
                w[k] = gvv ? pk2(wr[2 * k], wr[2 * k + 1]) : 0ull;
        }
        const float wi = swih[gvv ? tid : 0];
        const float bj = sbj[gvv ? tid : 0];

        auto gemv = [&](const float* hsrc, float xt, float* gout) {
            const ulonglong2* hq = (const ulonglong2*)hsrc;
            unsigned long long ax = 0ull, ay = 0ull;
#pragma unroll
            for (int k = 0; k < 27; k++) {
                ulonglong2 hv = hq[k];
                ff2(ax, w[2 * k],     hv.x);
                ff2(ay, w[2 * k + 1], hv.y);
            }
            ff2(ax, w[54], ((const unsigned long long*)hsrc)[54]);
            if (gvv) {
                float2 vx = upk2(ax), vy = upk2(ay);
                gout[tid] = (vx.x + vx.y) + (vy.x + vy.y) + fmaf(xt, wi, bj);
            }
        };

        for (int t = 0; t < T_STEPS; t++) {
            gemv(smh[0], sx[0][t], smgA);            // lane0 gates(t)
            __syncthreads();
            gemv(smh[1], sx[1][t], smgB);            // lane1 gates(t)
            __syncthreads();
        }
    } else {
        // ======== PW role (warps 14,15): contiguous 55-dim split ========
        const int wid2  = warp - 14;                 // 0 or 1
        const int dbase = wid2 * 55;                 // my dim range start
        float u0 = 1.0f, u1 = 1.0f;
        bool  a0 = true, a1 = true;

        // finish u update for a step (spart written >=2 bars ago)
        auto uchain = [&](int l, float& u, bool& a) {
            float du = sigm_precise(spart[l][0] + spart[l][1] + bp);
            u = a ? du : u + fminf(du, 1.0f - u);
            a = (rintf(u) != 0.0f);
        };
        // LSTM cell update for lane l (contiguous dims -> 1 wavefront/access)
        auto pwstate = [&](const float* g, int l, bool a) {
            if (a) {
#pragma unroll
                for (int i = 0; i < 2; i++) {
                    const int dd = lane + 32 * i;
                    if (dd < 55) {
                        const int d = dbase + dd;
                        float i_ = sigmf(g[d]);
                        float f_ = sigmf(g[HDIM + d]);
                        float g_ = tanha(g[2 * HDIM + d]);
                        float o_ = sigmf(g[3 * HDIM + d]);
                        float cn = f_ * smc[l][d] + i_ * g_;
                        smc[l][d] = cn;
                        smh[l][d] = o_ * tanha(cn);
                    }
                }
            }
        };
        // du partial over OWN dims only (no cross-warp c dependency)
        auto pwdu = [&](int l) {
            float p = 0.0f;
#pragma unroll
            for (int i = 0; i < 2; i++) {
                const int dd = lane + 32 * i;
                if (dd < 55) {
                    const int d = dbase + dd;
                    p = fmaf(smc[l][d], swp[d], p);
                }
            }
#pragma unroll
            for (int off = 16; off; off >>= 1)
                p += __shfl_xor_sync(0xffffffffu, p, off);
            if (lane == 0) spart[l][wid2] = p;
        };

        for (int t = 0; t < T_STEPS; t++) {
            // phase A: lane1, step t-1 (concurrent with GEMV lane0(t))
            if (t > 0) {
                const int s = t - 1;
                if (s > 0) uchain(1, u1, a1);
                totu += a1 ? 1 : 0;
                pwstate(smgB, 1, a1);
                pwdu(1);
            }
            __syncthreads();
            // phase B: lane0, step t (concurrent with GEMV lane1(t))
            if (t > 0) uchain(0, u0, a0);
            totu += a0 ? 1 : 0;
            pwstate(smgA, 0, a0);
            pwdu(0);
            __syncthreads();
        }
        // epilogue: lane1's final step (gates of t = T-1)
        uchain(1, u1, a1);
        totu += a1 ? 1 : 0;
        pwstate(smgB, 1, a1);
    }
    __syncthreads();

    // ---- FC head ----
    for (int pi = warp; pi < 2 * NCLS; pi += NTH / 32) {
        const int b = pi / NCLS, cls = pi % NCLS;
        const float* wf = Wfc + cls * HDIM;
        float s = 0.0f;
        for (int d = lane; d < HDIM; d += 32) s += smh[b][d] * wf[d];
#pragma unroll
        for (int off = 16; off; off >>= 1)
            s += __shfl_xor_sync(0xffffffffu, s, off);
        if (lane == 0) out[(b0g + b) * NCLS + cls] = s + bfc[cls];
    }

    // total_u: PW warps hold identical totu (both lanes); add once
    if (warp == 14 && lane == 0) atomicAdd(&out[last_idx], (float)totu);
}

extern "C" void kernel_launch(void* const* d_in, const int* in_sizes, int n_in,
                              void* d_out, int out_size) {
    const float* x    = (const float*)d_in[0];
    const float* Wih  = (const float*)d_in[1];
    const float* Whh  = (const float*)d_in[2];
    const float* bg   = (const float*)d_in[3];
    const float* Wp   = (const float*)d_in[4];
    const float* bp   = (const float*)d_in[5];
    const float* h0   = (const float*)d_in[6];
    const float* c0   = (const float*)d_in[7];
    const float* Wfc  = (const float*)d_in[8];
    const float* bfc  = (const float*)d_in[9];
    float* out = (float*)d_out;

    const int B = in_sizes[0] / T_STEPS;   // I = 1
    const int last = out_size - 1;

    zero_slot_kernel<<<1, 1>>>(out, last);
    skiplstm_kernel<<<B / 2, NTH>>>(x, Wih, Whh, bg, Wp, bp, h0, c0,
                                    Wfc, bfc, out, last);
}

// round 17
// speedup vs baseline: 1.2645x; 1.0225x over previous
#include <cuda_runtime.h>

#define T_STEPS 784
#define HDIM    110
#define G4      440
#define NTH     512
#define NCLS    10

// ---------- f32x2 packed helpers ----------
__device__ __forceinline__ unsigned long long pk2(float x, float y) {
    unsigned long long r;
    asm("mov.b64 %0, {%1,%2};" : "=l"(r) : "f"(x), "f"(y));
    return r;
}
__device__ __forceinline__ float2 upk2(unsigned long long a) {
    float2 r;
    asm("mov.b64 {%0,%1}, %2;" : "=f"(r.x), "=f"(r.y) : "l"(a));
    return r;
}
__device__ __forceinline__ void ff2(unsigned long long& acc,
                                    unsigned long long a,
                                    unsigned long long b) {
    asm("fma.rn.f32x2 %0, %1, %2, %0;" : "+l"(acc) : "l"(a), "l"(b));
}

// ---------- activations ----------
__device__ __forceinline__ float tanha(float x) {          // MUFU.TANH
    float r;
    asm("tanh.approx.f32 %0, %1;" : "=f"(r) : "f"(x));
    return r;
}
__device__ __forceinline__ float sigmf(float x) {          // fast gate sigmoid
    return fmaf(0.5f, tanha(0.5f * x), 0.5f);
}
__device__ __forceinline__ float sigm_precise(float x) {   // du decision path
    return __fdividef(1.0f, 1.0f + __expf(-x));
}

__global__ void zero_slot_kernel(float* o, int idx) { o[idx] = 0.0f; }

__global__ void __launch_bounds__(NTH, 1) skiplstm_kernel(
    const float* __restrict__ x,      // [B, T, 1]
    const float* __restrict__ Wih,    // [440, 1]
    const float* __restrict__ Whh,    // [440, 110]
    const float* __restrict__ bg,     // [440]
    const float* __restrict__ Wp,     // [1, 110]
    const float* __restrict__ bp_,    // [1]
    const float* __restrict__ h0,     // [110]
    const float* __restrict__ c0,     // [110]
    const float* __restrict__ Wfc,    // [10, 110]
    const float* __restrict__ bfc,    // [10]
    float* __restrict__ out,          // [B*10 + 1]
    int last_idx)
{
    __shared__ float sx[2][T_STEPS];                 // per-batch x sequence
    __shared__ __align__(16) float smh[2][112];      // h state (pads=0)
    __shared__ __align__(16) float smc[2][112];      // c state (pads=0)
    __shared__ float smgA[448];                      // gates lane0 (8 junk rows)
    __shared__ float smgB[448];                      // gates lane1
    __shared__ float swp[112];                       // W_p (zero-padded)
    __shared__ float swih[G4];                       // W_ih column
    __shared__ float sbj[G4];                        // gate bias
    __shared__ float spart[2][2];                    // du partials [lane][pw-warp]

    const int tid  = threadIdx.x;
    const int warp = tid >> 5, lane = tid & 31;
    const int b0g  = blockIdx.x * 2;

    for (int i = tid; i < T_STEPS; i += NTH) {
        sx[0][i] = x[b0g * T_STEPS + i];
        sx[1][i] = x[(b0g + 1) * T_STEPS + i];
    }
    for (int i = tid; i < 112; i += NTH) {
        float hv = (i < HDIM) ? h0[i] : 0.0f;
        float cv = (i < HDIM) ? c0[i] : 0.0f;
        smh[0][i] = hv; smh[1][i] = hv;
        smc[0][i] = cv; smc[1][i] = cv;
        swp[i] = (i < HDIM) ? Wp[i] : 0.0f;
    }
    if (tid < G4) {
        swih[tid] = Wih[tid];
        sbj[tid]  = bg[tid];
    }
    const float bp = bp_[0];
    __syncthreads();

    int totu = 0;

    if (warp < 14) {
        // ================= GEMV role (warps 0-13) =================
        const bool gvv = (tid < G4);
        unsigned long long w[55];                    // loaded ONLY on this path
        {
            const float* wr = Whh + (gvv ? tid : 0) * HDIM;
#pragma unroll
            for (int k = 0; k < 55; k++)
                w[k] = gvv ? pk2(wr[2 * k], wr[2 * k + 1]) : 0ull;
        }
        const float wi = swih[gvv ? tid : 0];
        const float bj = sbj[gvv ? tid : 0];

        auto gemv = [&](const float* hsrc, float xt, float* gout) {
            const ulonglong2* hq = (const ulonglong2*)hsrc;
            unsigned long long ax = 0ull, ay = 0ull;
#pragma unroll
            for (int k = 0; k < 27; k++) {
                ulonglong2 hv = hq[k];
                ff2(ax, w[2 * k],     hv.x);
                ff2(ay, w[2 * k + 1], hv.y);
            }
            ff2(ax, w[54], ((const unsigned long long*)hsrc)[54]);
            float2 vx = upk2(ax), vy = upk2(ay);
            gout[tid] = (vx.x + vx.y) + (vy.x + vy.y) + fmaf(xt, wi, bj);
        };

        for (int t = 0; t < T_STEPS; t++) {
            gemv(smh[0], sx[0][t], smgA);            // lane0 gates(t)
            __syncthreads();
            gemv(smh[1], sx[1][t], smgB);            // lane1 gates(t)
            __syncthreads();
        }
    } else {
        // ======== PW role (warps 14,15): contiguous 55-dim split ========
        const int wid2  = warp - 14;                 // 0 or 1
        const int dbase = wid2 * 55;                 // my dim range start
        float u0 = 1.0f, u1 = 1.0f;
        bool  a0 = true, a1 = true;

        // full PW for lane l, step s: loads first, uchain overlapped,
        // predicated stores, then du-partial (off-critical)
        auto pwork = [&](const float* g, int l, int s, float& u, bool& a) {
            // --- 1. unconditional loads (latency overlaps uchain) ---
            float gi[2], gf[2], gg[2], go[2], co[2];
#pragma unroll
            for (int i = 0; i < 2; i++) {
                const int dd = lane + 32 * i;
                const int d  = dbase + ((dd < 55) ? dd : 54);  // clamped dup
                gi[i] = g[d];
                gf[i] = g[HDIM + d];
                gg[i] = g[2 * HDIM + d];
                go[i] = g[3 * HDIM + d];
                co[i] = smc[l][d];
            }
            // --- 2. u chain (spart written >=2 bars ago) ---
            if (s > 0) {
                float du = sigm_precise(spart[l][0] + spart[l][1] + bp);
                u = a ? du : u + fminf(du, 1.0f - u);
                a = (rintf(u) != 0.0f);
            }
            totu += a ? 1 : 0;
            // --- 3. gate math + predicated stores + du partial ---
            float p = 0.0f;
#pragma unroll
            for (int i = 0; i < 2; i++) {
                const int dd = lane + 32 * i;
                float i_ = sigmf(gi[i]);
                float f_ = sigmf(gf[i]);
                float g_ = tanha(gg[i]);
                float o_ = sigmf(go[i]);
                float cnn = fmaf(f_, co[i], i_ * g_);
                float cn  = a ? cnn : co[i];
                if (dd < 55) {
                    const int d = dbase + dd;
                    p = fmaf(cn, swp[d], p);
                    if (a) {
                        smc[l][d] = cnn;
                        smh[l][d] = o_ * tanha(cnn);
                    }
                }
            }
#pragma unroll
            for (int off = 16; off; off >>= 1)
                p += __shfl_xor_sync(0xffffffffu, p, off);
            if (lane == 0) spart[l][wid2] = p;
        };

        for (int t = 0; t < T_STEPS; t++) {
            // phase A: lane1, step t-1 (concurrent with GEMV lane0(t))
            if (t > 0) pwork(smgB, 1, t - 1, u1, a1);
            __syncthreads();
            // phase B: lane0, step t (concurrent with GEMV lane1(t))
            pwork(smgA, 0, t, u0, a0);
            __syncthreads();
        }
        // epilogue: lane1's final step (gates of t = T-1)
        pwork(smgB, 1, T_STEPS - 1, u1, a1);
    }
    __syncthreads();

    // ---- FC head ----
    for (int pi = warp; pi < 2 * NCLS; pi += NTH / 32) {
        const int b = pi / NCLS, cls = pi % NCLS;
        const float* wf = Wfc + cls * HDIM;
        float s = 0.0f;
        for (int d = lane; d < HDIM; d += 32) s += smh[b][d] * wf[d];
#pragma unroll
        for (int off = 16; off; off >>= 1)
            s += __shfl_xor_sync(0xffffffffu, s, off);
        if (lane == 0) out[(b0g + b) * NCLS + cls] = s + bfc[cls];
    }

    // total_u: PW warps hold identical totu (both lanes); add once
    if (warp == 14 && lane == 0) atomicAdd(&out[last_idx], (float)totu);
}

extern "C" void kernel_launch(void* const* d_in, const int* in_sizes, int n_in,
                              void* d_out, int out_size) {
    const float* x    = (const float*)d_in[0];
    const float* Wih  = (const float*)d_in[1];
    const float* Whh  = (const float*)d_in[2];
    const float* bg   = (const float*)d_in[3];
    const float* Wp   = (const float*)d_in[4];
    const float* bp   = (const float*)d_in[5];
    const float* h0   = (const float*)d_in[6];
    const float* c0   = (const float*)d_in[7];
    const float* Wfc  = (const float*)d_in[8];
    const float* bfc  = (const float*)d_in[9];
    float* out = (float*)d_out;

    const int B = in_sizes[0] / T_STEPS;   // I = 1
    const int last = out_size - 1;

    zero_slot_kernel<<<1, 1>>>(out, last);
    skiplstm_kernel<<<B / 2, NTH>>>(x, Wih, Whh, bg, Wp, bp, h0, c0,
                                    Wfc, bfc, out, last);
}